// round 9
// baseline (speedup 1.0000x reference)
#include <cuda_runtime.h>

#define NN 50000
#define EE 800000
#define HH 128
#define CUTOFF_V 10.0f

// ---------------- device scratch (no allocations allowed) ----------------
__device__ float g_W[(size_t)EE * HH];     // edge gate rows (only active rows valid)
__device__ float g_hA[NN * HH];
__device__ float g_hB[NN * HH];
__device__ float g_agg[NN * HH];
__device__ int g_active[EE];
__device__ unsigned char g_mask[EE];
__device__ int g_count;

// ---------------- f32x2 packed-FMA helpers (Blackwell) ----------------
__device__ __forceinline__ void fma2(unsigned long long& d, unsigned long long a, unsigned long long b) {
    asm("fma.rn.f32x2 %0, %1, %2, %0;" : "+l"(d) : "l"(a), "l"(b));
}
__device__ __forceinline__ float2 up2(unsigned long long v) {
    float2 f;
    asm("mov.b64 {%0, %1}, %2;" : "=f"(f.x), "=f"(f.y) : "l"(v));
    return f;
}

// Weight fill: src row-major [128 k][128 c] -> pair-interleaved, lane-permuted:
//   word(dst) = (k>>1)*256 + ((c&3)*32 + (c>>2))*2 + (k&1)
// so thread cg's 4 columns (cg*4+j) sit at conflict-free LDS.64 slots.
__device__ __forceinline__ void fill_wp(float* __restrict__ dst, const float* __restrict__ src, int tid) {
    for (int i = tid; i < 4096; i += 256) {
        int k = i >> 5, c4 = (i & 31) * 4;
        float4 w = reinterpret_cast<const float4*>(src)[i];
        int base = (k >> 1) * 256 + (k & 1);
        dst[base + (((c4 + 0) & 3) * 32 + ((c4 + 0) >> 2)) * 2] = w.x;
        dst[base + (((c4 + 1) & 3) * 32 + ((c4 + 1) >> 2)) * 2] = w.y;
        dst[base + (((c4 + 2) & 3) * 32 + ((c4 + 2) >> 2)) * 2] = w.z;
        dst[base + (((c4 + 3) & 3) * 32 + ((c4 + 3) >> 2)) * 2] = w.w;
    }
}

// 64x128 @ 128x128 register-tiled GEMM, K-paired f32x2.
// sA: row-major [64][128]. sWp: pair-permuted (see fill_wp).
// acc[i][j]: (even-k, odd-k) partial sums for row rg*8+i, col cg*4+j.
__device__ __forceinline__ void gemm128(const float* __restrict__ sA,
                                        const float* __restrict__ sWp,
                                        int rg, int cg, unsigned long long acc[8][4]) {
    const float* a0 = sA + rg * (8 * 128);
    const float* w0 = sWp + cg * 2;
#pragma unroll 2
    for (int kp = 0; kp < 64; kp += 2) {
        const float* wk0 = w0 + kp * 256;
        unsigned long long b00 = *reinterpret_cast<const unsigned long long*>(wk0);
        unsigned long long b01 = *reinterpret_cast<const unsigned long long*>(wk0 + 64);
        unsigned long long b02 = *reinterpret_cast<const unsigned long long*>(wk0 + 128);
        unsigned long long b03 = *reinterpret_cast<const unsigned long long*>(wk0 + 192);
        unsigned long long b10 = *reinterpret_cast<const unsigned long long*>(wk0 + 256);
        unsigned long long b11 = *reinterpret_cast<const unsigned long long*>(wk0 + 320);
        unsigned long long b12 = *reinterpret_cast<const unsigned long long*>(wk0 + 384);
        unsigned long long b13 = *reinterpret_cast<const unsigned long long*>(wk0 + 448);
        const int k = kp * 2;
#pragma unroll
        for (int i = 0; i < 8; ++i) {
            ulonglong2 ap = *reinterpret_cast<const ulonglong2*>(a0 + i * 128 + k);
            fma2(acc[i][0], ap.x, b00);
            fma2(acc[i][1], ap.x, b01);
            fma2(acc[i][2], ap.x, b02);
            fma2(acc[i][3], ap.x, b03);
            fma2(acc[i][0], ap.y, b10);
            fma2(acc[i][1], ap.y, b11);
            fma2(acc[i][2], ap.y, b12);
            fma2(acc[i][3], ap.y, b13);
        }
    }
}

// ---------------- small kernels ----------------
__global__ void k_init() { g_count = 0; }

// mask + warp-aggregated compaction of active edges (E divisible by 256)
__global__ void __launch_bounds__(256) k_compact(const float* __restrict__ elen) {
    int e = blockIdx.x * 256 + threadIdx.x;
    int lane = threadIdx.x & 31;
    bool a = (elen[e] <= CUTOFF_V);
    g_mask[e] = a ? (unsigned char)1 : (unsigned char)0;
    unsigned m = __ballot_sync(0xffffffffu, a);
    int cnt = __popc(m);
    int base = 0;
    if (lane == 0 && cnt) base = atomicAdd(&g_count, cnt);
    base = __shfl_sync(0xffffffffu, base, 0);
    if (a) {
        int off = __popc(m & ((1u << lane) - 1u));
        g_active[base + off] = e;
    }
}

// message + scatter-add: one warp per edge, 4 floats per lane.
__global__ void __launch_bounds__(256) k_message(const int* __restrict__ ei,
                                                 const float* __restrict__ hin) {
    int idx = blockIdx.x * 256 + threadIdx.x;  // exactly E*32 threads
    int e = idx >> 5;
    int c4 = idx & 31;
    int s = __ldg(ei + e);
    float4 m = __ldg(reinterpret_cast<const float4*>(hin) + s * 32 + c4);
    if (g_mask[e]) {
        float4 wv = __ldcs(reinterpret_cast<const float4*>(g_W + (size_t)e * HH) + c4);
        m.x += wv.x; m.y += wv.y; m.z += wv.z; m.w += wv.w;
    }
    m.x = fmaxf(m.x, 0.f); m.y = fmaxf(m.y, 0.f);
    m.z = fmaxf(m.z, 0.f); m.w = fmaxf(m.w, 0.f);
    int d = __ldg(ei + EE + e);
    float* ap = g_agg + (size_t)d * HH + c4 * 4;
    asm volatile("red.global.add.v4.f32 [%0], {%1,%2,%3,%4};"
                 :: "l"(ap), "f"(m.x), "f"(m.y), "f"(m.z), "f"(m.w) : "memory");
}

// ---------------- fused 2-layer MLP (both weight mats in shared, exact fp32) ----------------
// MODE 0: edge gate  : rows = g_count (compacted), in = edge_attr[g_active[r]], out = g_W[e]
// MODE 1: node update: in = g_agg + hin (agg zeroed after read), out = relu(mlp(in)) + hin
// MODE 2: node update: same but no final relu (last conv)
template <int MODE>
__global__ void __launch_bounds__(256, 1) k_mlp2(const float* __restrict__ inp,
                                                 const float* __restrict__ hin,
                                                 const float* __restrict__ wa,
                                                 const float* __restrict__ ba,
                                                 const float* __restrict__ wb,
                                                 const float* __restrict__ bb,
                                                 float* __restrict__ hout) {
    extern __shared__ float sm[];
    float* sWa = sm;            // 16384 floats (pair-permuted)
    float* sWb = sm + 16384;    // 16384 (pair-permuted)
    float* sIn = sm + 32768;    // 8192 (row-major 64x128)
    float* sHid = sm + 40960;   // 8192   (total 192 KB)

    fill_wp(sWa, wa, threadIdx.x);
    fill_wp(sWb, wb, threadIdx.x);
    __syncthreads();  // weights visible before first gemm

    const int rows = (MODE == 0) ? g_count : NN;
    const int ntiles = (rows + 63) >> 6;
    const int rg = threadIdx.x >> 5, cg = threadIdx.x & 31;
    const float4 bav = reinterpret_cast<const float4*>(ba)[cg];
    const float4 bbv = reinterpret_cast<const float4*>(bb)[cg];
    const float4 z4 = make_float4(0.f, 0.f, 0.f, 0.f);

    for (int t = blockIdx.x; t < ntiles; t += gridDim.x) {
        const int base = t << 6;
        // load 64x128 input tile
        for (int i = threadIdx.x; i < 2048; i += 256) {
            int r = i >> 5, c4 = i & 31;
            int gr = base + r;
            float4 v = z4;
            if (gr < rows) {
                if constexpr (MODE == 0) {
                    int e = g_active[gr];
                    v = __ldcs(reinterpret_cast<const float4*>(inp + (size_t)e * HH) + c4);
                } else {
                    float4 x = reinterpret_cast<const float4*>(g_agg)[gr * 32 + c4];
                    reinterpret_cast<float4*>(g_agg)[gr * 32 + c4] = z4;  // fused zero for next conv
                    float4 y = __ldg(reinterpret_cast<const float4*>(hin) + gr * 32 + c4);
                    v = make_float4(x.x + y.x, x.y + y.y, x.z + y.z, x.w + y.w);
                }
            }
            reinterpret_cast<float4*>(sIn)[i] = v;
        }
        __syncthreads();  // S1: sIn ready (also guards prev-iter gemm2 sHid readers)

        unsigned long long acc[8][4];
#pragma unroll
        for (int i = 0; i < 8; ++i) { acc[i][0] = acc[i][1] = acc[i][2] = acc[i][3] = 0ULL; }
        gemm128(sIn, sWa, rg, cg, acc);
#pragma unroll
        for (int i = 0; i < 8; ++i) {
            float2 p0 = up2(acc[i][0]), p1 = up2(acc[i][1]), p2 = up2(acc[i][2]), p3 = up2(acc[i][3]);
            float4 v = make_float4(fmaxf(p0.x + p0.y + bav.x, 0.f),
                                   fmaxf(p1.x + p1.y + bav.y, 0.f),
                                   fmaxf(p2.x + p2.y + bav.z, 0.f),
                                   fmaxf(p3.x + p3.y + bav.w, 0.f));
            reinterpret_cast<float4*>(sHid + (rg * 8 + i) * 128)[cg] = v;
        }
        __syncthreads();  // S2: sHid ready (also guarantees all gemm1 sIn reads done)

#pragma unroll
        for (int i = 0; i < 8; ++i) { acc[i][0] = acc[i][1] = acc[i][2] = acc[i][3] = 0ULL; }
        gemm128(sHid, sWb, rg, cg, acc);
#pragma unroll
        for (int i = 0; i < 8; ++i) {
            int gr = base + rg * 8 + i;
            if (gr < rows) {
                float2 p0 = up2(acc[i][0]), p1 = up2(acc[i][1]), p2 = up2(acc[i][2]), p3 = up2(acc[i][3]);
                float4 v = make_float4(p0.x + p0.y + bbv.x, p1.x + p1.y + bbv.y,
                                       p2.x + p2.y + bbv.z, p3.x + p3.y + bbv.w);
                if constexpr (MODE == 0) {
                    int e = g_active[gr];
                    __stcs(reinterpret_cast<float4*>(g_W + (size_t)e * HH) + cg, v);
                } else {
                    if constexpr (MODE == 1) {
                        v.x = fmaxf(v.x, 0.f); v.y = fmaxf(v.y, 0.f);
                        v.z = fmaxf(v.z, 0.f); v.w = fmaxf(v.w, 0.f);
                    }
                    float4 hr = __ldg(reinterpret_cast<const float4*>(hin) + gr * 32 + cg);
                    v.x += hr.x; v.y += hr.y; v.z += hr.z; v.w += hr.w;
                    reinterpret_cast<float4*>(hout)[gr * 32 + cg] = v;
                }
            }
        }
        // next iteration's S1 provides the needed barrier before sIn/sHid reuse
    }
}

// ---------------- node embedding: x = relu(z@w0a+b0a)@w0b+b0b (K1=5) ----------------
// Also zero-initializes g_agg (so no separate zero kernel is needed for conv 0).
__global__ void __launch_bounds__(256) k_node_emb(const float* __restrict__ z,
                                                  const float* __restrict__ w0a,
                                                  const float* __restrict__ b0a,
                                                  const float* __restrict__ w0b,
                                                  const float* __restrict__ b0b) {
    extern __shared__ float sm[];
    float* sWb = sm;            // 16384 (pair-permuted)
    float* sHid = sm + 16384;   // 8192
    float* sWa = sm + 24576;    // 640
    fill_wp(sWb, w0b, threadIdx.x);
    for (int i = threadIdx.x; i < 640; i += 256) sWa[i] = w0a[i];
    __syncthreads();  // sWa/sWb fully written before first tile

    const int rg = threadIdx.x >> 5, cg = threadIdx.x & 31;
    const float4 bbv = reinterpret_cast<const float4*>(b0b)[cg];
    const float4 z4 = make_float4(0.f, 0.f, 0.f, 0.f);
    const int ntiles = (NN + 63) / 64;
    for (int t = blockIdx.x; t < ntiles; t += gridDim.x) {
        int base = t * 64;
        for (int i = threadIdx.x; i < 8192; i += 256) {
            int r = i >> 7, c = i & 127;
            int gr = base + r;
            float acc = 0.f;
            if (gr < NN) {
#pragma unroll
                for (int k = 0; k < 5; ++k)
                    acc = fmaf(__ldg(z + gr * 5 + k), sWa[k * 128 + c], acc);
                acc = fmaxf(acc + __ldg(b0a + c), 0.f);
            }
            sHid[i] = acc;
        }
        __syncthreads();
        unsigned long long acc[8][4];
#pragma unroll
        for (int i = 0; i < 8; ++i) { acc[i][0] = acc[i][1] = acc[i][2] = acc[i][3] = 0ULL; }
        gemm128(sHid, sWb, rg, cg, acc);
#pragma unroll
        for (int i = 0; i < 8; ++i) {
            int gr = base + rg * 8 + i;
            if (gr < NN) {
                float2 p0 = up2(acc[i][0]), p1 = up2(acc[i][1]), p2 = up2(acc[i][2]), p3 = up2(acc[i][3]);
                float4 v = make_float4(p0.x + p0.y + bbv.x, p1.x + p1.y + bbv.y,
                                       p2.x + p2.y + bbv.z, p3.x + p3.y + bbv.w);
                reinterpret_cast<float4*>(g_hA)[gr * 32 + cg] = v;
                reinterpret_cast<float4*>(g_agg)[gr * 32 + cg] = z4;  // init agg for conv 0
            }
        }
        __syncthreads();  // sHid reuse guard
    }
}

// ---------------- launch ----------------
extern "C" void kernel_launch(void* const* d_in, const int* in_sizes, int n_in,
                              void* d_out, int out_size) {
    const float* z    = (const float*)d_in[0];
    const int*   ei   = (const int*)d_in[1];
    const float* eatt = (const float*)d_in[2];
    const float* elen = (const float*)d_in[3];
    const float* w0a  = (const float*)d_in[4];
    const float* b0a  = (const float*)d_in[5];
    const float* w0b  = (const float*)d_in[6];
    const float* b0b  = (const float*)d_in[7];
    const float* w1a  = (const float*)d_in[8];
    const float* b1a  = (const float*)d_in[9];
    const float* w1b  = (const float*)d_in[10];
    const float* b1b  = (const float*)d_in[11];
    const float* w2a  = (const float*)d_in[12];
    const float* b2a  = (const float*)d_in[13];
    const float* w2b  = (const float*)d_in[14];
    const float* b2b  = (const float*)d_in[15];
    float* out = (float*)d_out;

    cudaFuncSetAttribute(k_mlp2<0>, cudaFuncAttributeMaxDynamicSharedMemorySize, 196608);
    cudaFuncSetAttribute(k_mlp2<1>, cudaFuncAttributeMaxDynamicSharedMemorySize, 196608);
    cudaFuncSetAttribute(k_mlp2<2>, cudaFuncAttributeMaxDynamicSharedMemorySize, 196608);
    cudaFuncSetAttribute(k_node_emb, cudaFuncAttributeMaxDynamicSharedMemorySize, 101376);

    float *hA, *hB;
    cudaGetSymbolAddress((void**)&hA, g_hA);
    cudaGetSymbolAddress((void**)&hB, g_hB);

    const int MSG_BLOCKS = (EE * 32) / 256;  // 100000

    k_init<<<1, 1>>>();
    k_compact<<<EE / 256, 256>>>(elen);
    k_node_emb<<<296, 256, 100864>>>(z, w0a, b0a, w0b, b0b);
    k_mlp2<0><<<148, 256, 196608>>>(eatt, nullptr, w2a, b2a, w2b, b2b, nullptr);

    // conv 0: hA -> hB   (agg zeroed by node_emb; mlp re-zeroes after reading)
    k_message<<<MSG_BLOCKS, 256>>>(ei, hA);
    k_mlp2<1><<<148, 256, 196608>>>(nullptr, hA, w1a, b1a, w1b, b1b, hB);

    // conv 1: hB -> hA
    k_message<<<MSG_BLOCKS, 256>>>(ei, hB);
    k_mlp2<1><<<148, 256, 196608>>>(nullptr, hB, w1a, b1a, w1b, b1b, hA);

    // conv 2: hA -> out (no inter-layer relu)
    k_message<<<MSG_BLOCKS, 256>>>(ei, hA);
    k_mlp2<2><<<148, 256, 196608>>>(nullptr, hA, w1a, b1a, w1b, b1b, out);
}

// round 10
// speedup vs baseline: 1.0184x; 1.0184x over previous
#include <cuda_runtime.h>

#define NN 50000
#define EE 800000
#define HH 128
#define CUTOFF_V 10.0f

// ---------------- device scratch (no allocations allowed) ----------------
__device__ float g_W[(size_t)EE * HH];     // edge gate rows (only active rows valid)
__device__ float g_hA[NN * HH];
__device__ float g_hB[NN * HH];
__device__ float g_agg[NN * HH];
__device__ int g_active[EE];
__device__ unsigned char g_mask[EE];
__device__ int g_count;

// ---------------- f32x2 packed-FMA helpers (Blackwell) ----------------
__device__ __forceinline__ void fma2(unsigned long long& d, unsigned long long a, unsigned long long b) {
    asm("fma.rn.f32x2 %0, %1, %2, %0;" : "+l"(d) : "l"(a), "l"(b));
}
__device__ __forceinline__ float2 up2(unsigned long long v) {
    float2 f;
    asm("mov.b64 {%0, %1}, %2;" : "=f"(f.x), "=f"(f.y) : "l"(v));
    return f;
}

// Weight layout: src row-major [128 k][128 c] ->
//   word(k,c) = (k>>1)*256 + ((c&1)*64 + (c>>1))*2 + (k&1)
// K-pairs interleaved; even cols in first 128 words of each kp-row, odd cols in
// second 128. Thread m (0..63) owns cols {2m, 2m+1}: its B loads are ull at
// word kp*256 + 2m (even col) and kp*256 + 128 + 2m (odd col) -> each warp's
// load is 32 lanes x 8B contiguous = conflict-free LDS.64.
__device__ __forceinline__ void fill_wp(float* __restrict__ dst, const float* __restrict__ src, int tid, int nthr) {
    for (int i = tid; i < 4096; i += nthr) {
        int k = i >> 5, c4 = (i & 31) * 4;
        float4 w = reinterpret_cast<const float4*>(src)[i];
        int base = (k >> 1) * 256 + (k & 1);
#pragma unroll
        for (int j = 0; j < 4; ++j) {
            int c = c4 + j;
            float val = (j == 0) ? w.x : (j == 1) ? w.y : (j == 2) ? w.z : w.w;
            dst[base + (((c & 1) * 64 + (c >> 1)) * 2)] = val;
        }
    }
}

// 64x128 @ 128x128 GEMM, K-paired f32x2, thread tile 8 rows x 2 cols.
// 512 threads: rg = tid>>6 (8 rowgroups of 8 rows), m = tid&63 (cols 2m, 2m+1).
// acc[i][0] -> col 2m, acc[i][1] -> col 2m+1; (lo,hi) = (even-k, odd-k) partials.
__device__ __forceinline__ void gemm128(const float* __restrict__ sA,
                                        const float* __restrict__ sWp,
                                        int rg, int m, unsigned long long acc[8][2]) {
    const float* a0 = sA + rg * (8 * 128);
    const float* w0 = sWp + m * 2;
#pragma unroll 4
    for (int kp = 0; kp < 64; kp += 2) {   // body = 2 k-pairs = 4 k
        const float* wb = w0 + kp * 256;
        unsigned long long b00 = *reinterpret_cast<const unsigned long long*>(wb);        // kp,   col 2m
        unsigned long long b10 = *reinterpret_cast<const unsigned long long*>(wb + 128);  // kp,   col 2m+1
        unsigned long long b01 = *reinterpret_cast<const unsigned long long*>(wb + 256);  // kp+1, col 2m
        unsigned long long b11 = *reinterpret_cast<const unsigned long long*>(wb + 384);  // kp+1, col 2m+1
        const int k = kp * 2;
#pragma unroll
        for (int i = 0; i < 8; ++i) {
            ulonglong2 ap = *reinterpret_cast<const ulonglong2*>(a0 + i * 128 + k);  // a[k..k+3], broadcast
            fma2(acc[i][0], ap.x, b00);
            fma2(acc[i][1], ap.x, b10);
            fma2(acc[i][0], ap.y, b01);
            fma2(acc[i][1], ap.y, b11);
        }
    }
}

// ---------------- small kernels ----------------
__global__ void k_init() { g_count = 0; }

// mask + warp-aggregated compaction of active edges (E divisible by 256)
__global__ void __launch_bounds__(256) k_compact(const float* __restrict__ elen) {
    int e = blockIdx.x * 256 + threadIdx.x;
    int lane = threadIdx.x & 31;
    bool a = (elen[e] <= CUTOFF_V);
    g_mask[e] = a ? (unsigned char)1 : (unsigned char)0;
    unsigned m = __ballot_sync(0xffffffffu, a);
    int cnt = __popc(m);
    int base = 0;
    if (lane == 0 && cnt) base = atomicAdd(&g_count, cnt);
    base = __shfl_sync(0xffffffffu, base, 0);
    if (a) {
        int off = __popc(m & ((1u << lane) - 1u));
        g_active[base + off] = e;
    }
}

__global__ void __launch_bounds__(256) k_zero_agg() {
    int i = blockIdx.x * 256 + threadIdx.x;  // exactly N*H/4 threads
    reinterpret_cast<float4*>(g_agg)[i] = make_float4(0.f, 0.f, 0.f, 0.f);
}

// message + scatter-add: one warp per edge, 4 floats per lane.
__global__ void __launch_bounds__(256) k_message(const int* __restrict__ ei,
                                                 const float* __restrict__ hin) {
    int idx = blockIdx.x * 256 + threadIdx.x;  // exactly E*32 threads
    int e = idx >> 5;
    int c4 = idx & 31;
    int s = __ldg(ei + e);
    float4 m = __ldg(reinterpret_cast<const float4*>(hin) + s * 32 + c4);
    if (g_mask[e]) {
        float4 wv = __ldcs(reinterpret_cast<const float4*>(g_W + (size_t)e * HH) + c4);
        m.x += wv.x; m.y += wv.y; m.z += wv.z; m.w += wv.w;
    }
    m.x = fmaxf(m.x, 0.f); m.y = fmaxf(m.y, 0.f);
    m.z = fmaxf(m.z, 0.f); m.w = fmaxf(m.w, 0.f);
    int d = __ldg(ei + EE + e);
    float* ap = g_agg + (size_t)d * HH + c4 * 4;
    asm volatile("red.global.add.v4.f32 [%0], {%1,%2,%3,%4};"
                 :: "l"(ap), "f"(m.x), "f"(m.y), "f"(m.z), "f"(m.w) : "memory");
}

// ---------------- fused 2-layer MLP, 512 threads (4 warps/SMSP) ----------------
// MODE 0: edge gate  : rows = g_count (compacted), in = edge_attr[g_active[r]], out = g_W[e]
// MODE 1: node update: in = g_agg + hin, out = relu(mlp(in)) + hin
// MODE 2: node update: in = g_agg + hin, out = mlp(in) + hin   (last conv)
template <int MODE>
__global__ void __launch_bounds__(512, 1) k_mlp2(const float* __restrict__ inp,
                                                 const float* __restrict__ hin,
                                                 const float* __restrict__ wa,
                                                 const float* __restrict__ ba,
                                                 const float* __restrict__ wb,
                                                 const float* __restrict__ bb,
                                                 float* __restrict__ hout) {
    extern __shared__ float sm[];
    float* sWa = sm;            // 16384 floats (pair-permuted)
    float* sWb = sm + 16384;    // 16384 (pair-permuted)
    float* sIn = sm + 32768;    // 8192 (row-major 64x128)
    float* sHid = sm + 40960;   // 8192   (total 192 KB)

    fill_wp(sWa, wa, threadIdx.x, 512);
    fill_wp(sWb, wb, threadIdx.x, 512);
    __syncthreads();  // weights visible before first gemm

    const int rows = (MODE == 0) ? g_count : NN;
    const int ntiles = (rows + 63) >> 6;
    const int rg = threadIdx.x >> 6;      // 0..7: rows rg*8..rg*8+7
    const int m = threadIdx.x & 63;       // cols 2m, 2m+1
    const float2 bav = reinterpret_cast<const float2*>(ba)[m];
    const float2 bbv = reinterpret_cast<const float2*>(bb)[m];

    for (int t = blockIdx.x; t < ntiles; t += gridDim.x) {
        const int base = t << 6;
        // load 64x128 input tile
        for (int i = threadIdx.x; i < 2048; i += 512) {
            int r = i >> 5, c4 = i & 31;
            int gr = base + r;
            float4 v = make_float4(0.f, 0.f, 0.f, 0.f);
            if (gr < rows) {
                if constexpr (MODE == 0) {
                    int e = g_active[gr];
                    v = __ldcs(reinterpret_cast<const float4*>(inp + (size_t)e * HH) + c4);
                } else {
                    float4 x = reinterpret_cast<const float4*>(g_agg)[gr * 32 + c4];
                    float4 y = __ldg(reinterpret_cast<const float4*>(hin) + gr * 32 + c4);
                    v = make_float4(x.x + y.x, x.y + y.y, x.z + y.z, x.w + y.w);
                }
            }
            reinterpret_cast<float4*>(sIn)[i] = v;
        }
        __syncthreads();  // S1: sIn ready (also guards prev-iter gemm2 sHid readers)

        unsigned long long acc[8][2];
#pragma unroll
        for (int i = 0; i < 8; ++i) { acc[i][0] = acc[i][1] = 0ULL; }
        gemm128(sIn, sWa, rg, m, acc);
#pragma unroll
        for (int i = 0; i < 8; ++i) {
            float2 p0 = up2(acc[i][0]), p1 = up2(acc[i][1]);
            float2 v = make_float2(fmaxf(p0.x + p0.y + bav.x, 0.f),
                                   fmaxf(p1.x + p1.y + bav.y, 0.f));
            reinterpret_cast<float2*>(sHid + (rg * 8 + i) * 128)[m] = v;
        }
        __syncthreads();  // S2: sHid ready (also guarantees all gemm1 sIn reads done)

#pragma unroll
        for (int i = 0; i < 8; ++i) { acc[i][0] = acc[i][1] = 0ULL; }
        gemm128(sHid, sWb, rg, m, acc);
#pragma unroll
        for (int i = 0; i < 8; ++i) {
            int gr = base + rg * 8 + i;
            if (gr < rows) {
                float2 p0 = up2(acc[i][0]), p1 = up2(acc[i][1]);
                float2 v = make_float2(p0.x + p0.y + bbv.x, p1.x + p1.y + bbv.y);
                if constexpr (MODE == 0) {
                    int e = g_active[gr];
                    __stcs(reinterpret_cast<float2*>(g_W + (size_t)e * HH) + m, v);
                } else {
                    if constexpr (MODE == 1) {
                        v.x = fmaxf(v.x, 0.f); v.y = fmaxf(v.y, 0.f);
                    }
                    float2 hr = __ldg(reinterpret_cast<const float2*>(hin) + gr * 64 + m);
                    v.x += hr.x; v.y += hr.y;
                    reinterpret_cast<float2*>(hout)[gr * 64 + m] = v;
                }
            }
        }
        // next iteration's S1 provides the needed barrier before sIn/sHid reuse
    }
}

// ---------------- node embedding: x = relu(z@w0a+b0a)@w0b+b0b (K1=5) ----------------
__global__ void __launch_bounds__(512) k_node_emb(const float* __restrict__ z,
                                                  const float* __restrict__ w0a,
                                                  const float* __restrict__ b0a,
                                                  const float* __restrict__ w0b,
                                                  const float* __restrict__ b0b) {
    extern __shared__ float sm[];
    float* sWb = sm;            // 16384 (pair-permuted)
    float* sHid = sm + 16384;   // 8192
    float* sWa = sm + 24576;    // 640
    fill_wp(sWb, w0b, threadIdx.x, 512);
    for (int i = threadIdx.x; i < 640; i += 512) sWa[i] = w0a[i];
    __syncthreads();  // sWa/sWb fully written before first tile

    const int rg = threadIdx.x >> 6;
    const int m = threadIdx.x & 63;
    const float2 bbv = reinterpret_cast<const float2*>(b0b)[m];
    const int ntiles = (NN + 63) / 64;
    for (int t = blockIdx.x; t < ntiles; t += gridDim.x) {
        int base = t * 64;
        for (int i = threadIdx.x; i < 8192; i += 512) {
            int r = i >> 7, c = i & 127;
            int gr = base + r;
            float acc = 0.f;
            if (gr < NN) {
#pragma unroll
                for (int k = 0; k < 5; ++k)
                    acc = fmaf(__ldg(z + gr * 5 + k), sWa[k * 128 + c], acc);
                acc = fmaxf(acc + __ldg(b0a + c), 0.f);
            }
            sHid[i] = acc;
        }
        __syncthreads();
        unsigned long long acc[8][2];
#pragma unroll
        for (int i = 0; i < 8; ++i) { acc[i][0] = acc[i][1] = 0ULL; }
        gemm128(sHid, sWb, rg, m, acc);
#pragma unroll
        for (int i = 0; i < 8; ++i) {
            int gr = base + rg * 8 + i;
            if (gr < NN) {
                float2 p0 = up2(acc[i][0]), p1 = up2(acc[i][1]);
                float2 v = make_float2(p0.x + p0.y + bbv.x, p1.x + p1.y + bbv.y);
                reinterpret_cast<float2*>(g_hA)[gr * 64 + m] = v;
            }
        }
        __syncthreads();  // sHid reuse guard
    }
}

// ---------------- launch ----------------
extern "C" void kernel_launch(void* const* d_in, const int* in_sizes, int n_in,
                              void* d_out, int out_size) {
    const float* z    = (const float*)d_in[0];
    const int*   ei   = (const int*)d_in[1];
    const float* eatt = (const float*)d_in[2];
    const float* elen = (const float*)d_in[3];
    const float* w0a  = (const float*)d_in[4];
    const float* b0a  = (const float*)d_in[5];
    const float* w0b  = (const float*)d_in[6];
    const float* b0b  = (const float*)d_in[7];
    const float* w1a  = (const float*)d_in[8];
    const float* b1a  = (const float*)d_in[9];
    const float* w1b  = (const float*)d_in[10];
    const float* b1b  = (const float*)d_in[11];
    const float* w2a  = (const float*)d_in[12];
    const float* b2a  = (const float*)d_in[13];
    const float* w2b  = (const float*)d_in[14];
    const float* b2b  = (const float*)d_in[15];
    float* out = (float*)d_out;

    cudaFuncSetAttribute(k_mlp2<0>, cudaFuncAttributeMaxDynamicSharedMemorySize, 196608);
    cudaFuncSetAttribute(k_mlp2<1>, cudaFuncAttributeMaxDynamicSharedMemorySize, 196608);
    cudaFuncSetAttribute(k_mlp2<2>, cudaFuncAttributeMaxDynamicSharedMemorySize, 196608);
    cudaFuncSetAttribute(k_node_emb, cudaFuncAttributeMaxDynamicSharedMemorySize, 101376);

    float *hA, *hB;
    cudaGetSymbolAddress((void**)&hA, g_hA);
    cudaGetSymbolAddress((void**)&hB, g_hB);

    const int ZERO_BLOCKS = (NN * HH / 4) / 256;  // 6250
    const int MSG_BLOCKS  = (EE * 32) / 256;      // 100000

    k_init<<<1, 1>>>();
    k_compact<<<EE / 256, 256>>>(elen);
    k_node_emb<<<296, 512, 100864>>>(z, w0a, b0a, w0b, b0b);
    k_mlp2<0><<<148, 512, 196608>>>(eatt, nullptr, w2a, b2a, w2b, b2b, nullptr);

    // conv 0: hA -> hB
    k_zero_agg<<<ZERO_BLOCKS, 256>>>();
    k_message<<<MSG_BLOCKS, 256>>>(ei, hA);
    k_mlp2<1><<<148, 512, 196608>>>(nullptr, hA, w1a, b1a, w1b, b1b, hB);

    // conv 1: hB -> hA
    k_zero_agg<<<ZERO_BLOCKS, 256>>>();
    k_message<<<MSG_BLOCKS, 256>>>(ei, hB);
    k_mlp2<1><<<148, 512, 196608>>>(nullptr, hB, w1a, b1a, w1b, b1b, hA);

    // conv 2: hA -> out (no inter-layer relu)
    k_zero_agg<<<ZERO_BLOCKS, 256>>>();
    k_message<<<MSG_BLOCKS, 256>>>(ei, hA);
    k_mlp2<2><<<148, 512, 196608>>>(nullptr, hA, w1a, b1a, w1b, b1b, out);
}